// round 11
// baseline (speedup 1.0000x reference)
#include <cuda_runtime.h>
#include <cstdint>

#define NUM_T 15

// Branchless 4-level binary search + LUT lookup, all in one asm block.
// c = #{i : x >= t_i}; returns L[c]. Tables in shared memory at tsh
// (t at +0, L at +64). Conflict-free: both tables < 128B.
__device__ __forceinline__ float bucket(float x, float t7, float t11, float t3,
                                        unsigned tsh)
{
    float y;
    asm volatile(
        "{\n\t"
        ".reg .pred p;\n\t"
        ".reg .f32 tv;\n\t"
        ".reg .u32 off;\n\t"
        "setp.ge.f32 p, %1, %2;\n\t"      // level 1: x >= t[7] ?
        "selp.f32 tv, %3, %4, p;\n\t"     // pivot2 = p ? t[11] : t[3]
        "selp.u32 off, 32, 0, p;\n\t"     // idx bytes: 8*4 or 0
        "setp.ge.f32 p, %1, tv;\n\t"      // level 2
        "@p add.u32 off, off, 16;\n\t"    // += 4*4
        "add.u32 off, off, %5;\n\t"       // off = tsh + 4*idx4
        "ld.shared.f32 tv, [off+4];\n\t"  // t[idx4+1]
        "setp.ge.f32 p, %1, tv;\n\t"      // level 3
        "@p add.u32 off, off, 8;\n\t"     // += 2*4
        "ld.shared.f32 tv, [off];\n\t"    // t[idx2]
        "setp.ge.f32 p, %1, tv;\n\t"      // level 4
        "@p add.u32 off, off, 4;\n\t"     // off = tsh + 4*c
        "ld.shared.f32 %0, [off+64];\n\t" // L[c]
        "}\n\t"
        : "=f"(y)
        : "f"(x), "f"(t7), "f"(t11), "f"(t3), "r"(tsh));
    return y;
}

__device__ __forceinline__ void quad_bucket(float4& r, const float4& v,
                                            float t7, float t11, float t3,
                                            unsigned tsh)
{
    r.x = bucket(v.x, t7, t11, t3, tsh);
    r.y = bucket(v.y, t7, t11, t3, tsh);
    r.z = bucket(v.z, t7, t11, t3, tsh);
    r.w = bucket(v.w, t7, t11, t3, tsh);
}

// Persistent single-wave kernel: 1024 CTAs x 256 thr, all co-resident
// (launch_bounds min 7 CTA/SM caps regs at 36). Each thread loops `iters`
// times over stride-2^18 float4 pairs (MLP=2, no bounds checks when the
// grid divides n4). LUT built once per CTA instead of once per tile.
__global__ __launch_bounds__(256, 7)
void kq_kernel_pers(const float4* __restrict__ x,
                    float4* __restrict__ y,
                    const float* __restrict__ th,
                    const float* __restrict__ al,
                    const float* __restrict__ bp,
                    unsigned iters)
{
    __shared__ float s[32];

    // Build table: s[0..14] = thresholds, s[15] = pad,
    // s[16+k] = L[k] = b + sum_{j<k} alpha_j (left-assoc = reference order).
    if (threadIdx.x < 32) {
        int i = threadIdx.x;
        float val;
        if (i < 16) {
            val = (i < NUM_T) ? __ldg(th + i) : 0.0f;
        } else {
            int k = i - 16;
            float L = __ldg(bp);
#pragma unroll
            for (int j = 0; j < NUM_T; j++) {
                float aj = __ldg(al + j);
                if (j < k) L += aj;   // predicated, order-preserving
            }
            val = L;
        }
        s[i] = val;
    }
    __syncthreads();

    const unsigned tsh = (unsigned)__cvta_generic_to_shared(s);
    const float t7 = s[7], t11 = s[11], t3 = s[3];

    const unsigned NT = gridDim.x * blockDim.x;
    unsigned i0 = blockIdx.x * blockDim.x + threadIdx.x;

#pragma unroll 1
    for (unsigned it = 0; it < iters; ++it) {
        float4 v0 = x[i0];
        float4 v1 = x[i0 + NT];

        float4 r0, r1;
        quad_bucket(r0, v0, t7, t11, t3, tsh);
        quad_bucket(r1, v1, t7, t11, t3, tsh);

        y[i0] = r0;
        y[i0 + NT] = r1;
        i0 += 2u * NT;
    }
}

// Generic fallback (bounds-checked, scalar) — independent of the LUT.
__global__ void kq_tail(const float* __restrict__ x,
                        float* __restrict__ y,
                        const float* __restrict__ th,
                        const float* __restrict__ al,
                        const float* __restrict__ bp,
                        long long start, long long n)
{
    long long i = start + (long long)blockIdx.x * blockDim.x + threadIdx.x;
    if (i >= n) return;
    float v = x[i];
    float r = __ldg(bp);
#pragma unroll
    for (int k = 0; k < NUM_T; k++) {
        asm("{\n\t"
            ".reg .pred p;\n\t"
            "setp.ge.f32 p, %1, %2;\n\t"
            "@p add.f32 %0, %0, %3;\n\t"
            "}"
            : "+f"(r) : "f"(v), "f"(__ldg(th + k)), "f"(__ldg(al + k)));
    }
    y[i] = r;
}

extern "C" void kernel_launch(void* const* d_in, const int* in_sizes, int n_in,
                              void* d_out, int out_size)
{
    // Input order per setup_inputs: x, T, thresholds, alphas, b
    const float* x  = (const float*)d_in[0];
    // d_in[1] = T (backward-only, unused in forward)
    const float* th = (const float*)d_in[2];
    const float* al = (const float*)d_in[3];
    const float* bp = (const float*)d_in[4];
    float* y = (float*)d_out;

    const long long n = (long long)in_sizes[0];
    const long long n4 = n / 4;

    const int threads = 256;
    const int ctas = 1024;                         // single wave on 148 SMs @ 7/SM
    const long long NT = (long long)ctas * threads;       // 2^18 threads
    const long long per_iter = 2 * NT;                    // float4s per iteration

    const long long iters = n4 / per_iter;                // 32 for n4 = 2^24
    const long long covered = iters * per_iter * 4;       // elements covered

    if (iters > 0) {
        kq_kernel_pers<<<ctas, threads>>>(
            (const float4*)x, (float4*)y, th, al, bp, (unsigned)iters);
    }
    if (covered < n) {
        long long rem = n - covered;
        int tb = (int)((rem + 255) / 256);
        kq_tail<<<tb, 256>>>(x, y, th, al, bp, covered, n);
    }
}

// round 12
// speedup vs baseline: 1.1512x; 1.1512x over previous
#include <cuda_runtime.h>
#include <cstdint>

#define NUM_T 15

// Branchless 4-level binary search + LUT lookup, all in one asm block.
// c = #{i : x >= t_i}; returns L[c]. Tables in shared memory at tsh
// (t at +0, L at +64). Conflict-free: both tables < 128B.
__device__ __forceinline__ float bucket(float x, float t7, float t11, float t3,
                                        unsigned tsh)
{
    float y;
    asm volatile(
        "{\n\t"
        ".reg .pred p;\n\t"
        ".reg .f32 tv;\n\t"
        ".reg .u32 off;\n\t"
        "setp.ge.f32 p, %1, %2;\n\t"      // level 1: x >= t[7] ?
        "selp.f32 tv, %3, %4, p;\n\t"     // pivot2 = p ? t[11] : t[3]
        "selp.u32 off, 32, 0, p;\n\t"     // idx bytes: 8*4 or 0
        "setp.ge.f32 p, %1, tv;\n\t"      // level 2
        "@p add.u32 off, off, 16;\n\t"    // += 4*4
        "add.u32 off, off, %5;\n\t"       // off = tsh + 4*idx4
        "ld.shared.f32 tv, [off+4];\n\t"  // t[idx4+1]
        "setp.ge.f32 p, %1, tv;\n\t"      // level 3
        "@p add.u32 off, off, 8;\n\t"     // += 2*4
        "ld.shared.f32 tv, [off];\n\t"    // t[idx2]
        "setp.ge.f32 p, %1, tv;\n\t"      // level 4
        "@p add.u32 off, off, 4;\n\t"     // off = tsh + 4*c
        "ld.shared.f32 %0, [off+64];\n\t" // L[c]
        "}\n\t"
        : "=f"(y)
        : "f"(x), "f"(t7), "f"(t11), "f"(t3), "r"(tsh));
    return y;
}

// 256-bit global load/store (sm_10x LDG.E.256 / STG.E.256).
__device__ __forceinline__ void ldg256(float v[8], const float* p)
{
    asm volatile(
        "ld.global.nc.v8.f32 {%0,%1,%2,%3,%4,%5,%6,%7}, [%8];"
        : "=f"(v[0]), "=f"(v[1]), "=f"(v[2]), "=f"(v[3]),
          "=f"(v[4]), "=f"(v[5]), "=f"(v[6]), "=f"(v[7])
        : "l"(p));
}

__device__ __forceinline__ void stg256(float* p, const float v[8])
{
    asm volatile(
        "st.global.v8.f32 [%0], {%1,%2,%3,%4,%5,%6,%7,%8};"
        :: "l"(p),
           "f"(v[0]), "f"(v[1]), "f"(v[2]), "f"(v[3]),
           "f"(v[4]), "f"(v[5]), "f"(v[6]), "f"(v[7])
        : "memory");
}

// Single-launch kernel, R8 shape (8 floats/thread, 32768 CTAs x 256 thr)
// but with ONE 256-bit load and ONE 256-bit store per thread instead of
// 2x128-bit: same outstanding-line depth, half the memory instructions
// and L1tex wavefronts.
__global__ __launch_bounds__(256)
void kq_kernel_full(const float* __restrict__ x,
                    float* __restrict__ y,
                    const float* __restrict__ th,
                    const float* __restrict__ al,
                    const float* __restrict__ bp)
{
    __shared__ float s[32];

    const unsigned tid = blockIdx.x * blockDim.x + threadIdx.x;
    const float* xp = x + (size_t)tid * 8u;

    // Front-batched 256-bit load (independent of smem -> issue first).
    float v[8];
    ldg256(v, xp);

    // Build table: s[0..14] = thresholds, s[15] = pad,
    // s[16+k] = L[k] = b + sum_{j<k} alpha_j (left-assoc = reference order).
    if (threadIdx.x < 32) {
        int i = threadIdx.x;
        float val;
        if (i < 16) {
            val = (i < NUM_T) ? __ldg(th + i) : 0.0f;
        } else {
            int k = i - 16;
            float L = __ldg(bp);
#pragma unroll
            for (int j = 0; j < NUM_T; j++) {
                float aj = __ldg(al + j);
                if (j < k) L += aj;   // predicated, order-preserving
            }
            val = L;
        }
        s[i] = val;
    }
    __syncthreads();

    const unsigned tsh = (unsigned)__cvta_generic_to_shared(s);
    const float t7 = s[7], t11 = s[11], t3 = s[3];

    float r[8];
#pragma unroll
    for (int k = 0; k < 8; k++)
        r[k] = bucket(v[k], t7, t11, t3, tsh);

    stg256(y + (size_t)tid * 8u, r);
}

// Generic fallback (bounds-checked, scalar) — independent of the LUT.
__global__ void kq_tail(const float* __restrict__ x,
                        float* __restrict__ y,
                        const float* __restrict__ th,
                        const float* __restrict__ al,
                        const float* __restrict__ bp,
                        long long start, long long n)
{
    long long i = start + (long long)blockIdx.x * blockDim.x + threadIdx.x;
    if (i >= n) return;
    float v = x[i];
    float r = __ldg(bp);
#pragma unroll
    for (int k = 0; k < NUM_T; k++) {
        asm("{\n\t"
            ".reg .pred p;\n\t"
            "setp.ge.f32 p, %1, %2;\n\t"
            "@p add.f32 %0, %0, %3;\n\t"
            "}"
            : "+f"(r) : "f"(v), "f"(__ldg(th + k)), "f"(__ldg(al + k)));
    }
    y[i] = r;
}

extern "C" void kernel_launch(void* const* d_in, const int* in_sizes, int n_in,
                              void* d_out, int out_size)
{
    // Input order per setup_inputs: x, T, thresholds, alphas, b
    const float* x  = (const float*)d_in[0];
    // d_in[1] = T (backward-only, unused in forward)
    const float* th = (const float*)d_in[2];
    const float* al = (const float*)d_in[3];
    const float* bp = (const float*)d_in[4];
    float* y = (float*)d_out;

    const long long n = (long long)in_sizes[0];
    const int threads = 256;
    const long long per_block = (long long)threads * 8;  // floats per block
    const long long full_blocks = n / per_block;
    const long long covered = full_blocks * per_block;

    if (full_blocks > 0) {
        kq_kernel_full<<<(unsigned)full_blocks, threads>>>(x, y, th, al, bp);
    }
    if (covered < n) {
        long long rem = n - covered;
        int tb = (int)((rem + 255) / 256);
        kq_tail<<<tb, 256>>>(x, y, th, al, bp, covered, n);
    }
}